// round 3
// baseline (speedup 1.0000x reference)
#include <cuda_runtime.h>
#include <cuda_bf16.h>
#include <math.h>

typedef unsigned long long u64;

// ---------------------------------------------------------------------------
// Problem dims
// ---------------------------------------------------------------------------
#define LQ   4096            // L = 16*16*16
#define NC   128             // channels C
#define DI   256             // D_INNER
#define NSEQ 3               // directions
#define NROW (NSEQ*LQ)       // 12288
#define DST  16              // D_STATE
#define NCHUNK 64            // chunks per sequence
#define CHUNK  64            // chunk length

// ---------------------------------------------------------------------------
// Workspace (static device arrays — no cudaMalloc anywhere)
// ---------------------------------------------------------------------------
__device__ float g_norm[LQ * NC];
__device__ float g_xz  [NROW * 512];
__device__ float g_xc  [NROW * DI];
__device__ float g_xdbl[NROW * 40];
__device__ float g_e1  [NROW * DI];
__device__ float g_du  [NROW * DI];
__device__ float g_sz  [NROW * DI];
__device__ float g_S   [NSEQ * NCHUNK * DI * DST];
__device__ float g_p   [NSEQ * NCHUNK * DI];
__device__ float g_h0  [NSEQ * NCHUNK * DI * DST];
__device__ float g_yg  [NROW * DI];
__device__ float g_y   [NROW * NC];
__device__ float g_res [LQ * NC];
__device__ float g_hn  [LQ * NC];
__device__ float g_fc1 [LQ * 512];

// ---------------------------------------------------------------------------
// Helpers
// ---------------------------------------------------------------------------
__device__ __forceinline__ float fast_exp(float x) {
    x = fminf(fmaxf(x, -87.0f), 87.0f);
    float t = x * 1.4426950408889634f;
    float n = rintf(t);
    float f = t - n;
    float g = f * 0.6931471805599453f;
    float p = 1.0f + g * (1.0f + g * (0.5f + g * (0.16666667f + g * (0.041666668f +
              g * (0.008333334f + g * 0.0013888889f)))));
    float s = __int_as_float(((int)n + 127) << 23);
    return p * s;
}

__device__ __forceinline__ float softplusf_(float x) {
    if (x > 15.0f) return x;
    float y = fast_exp(x);
    if (y < 0.05f) {
        return y * (1.0f + y * (-0.5f + y * (0.33333334f + y * (-0.25f + y * 0.2f))));
    }
    return log1pf(y);
}

__device__ __forceinline__ float wsum(float v) {
    #pragma unroll
    for (int o = 16; o > 0; o >>= 1) v += __shfl_xor_sync(0xffffffffu, v, o);
    return v;
}

__device__ __forceinline__ void build_pows(float e1, float* e) {
    e[0] = 1.0f; e[1] = e1;
    #pragma unroll
    for (int j = 2; j <= 16; j++) e[j] = e[j >> 1] * e[j - (j >> 1)];
}

// packed f32x2 fma: d = a*b + c per 32-bit lane (2x fp32 throughput on sm_103a)
__device__ __forceinline__ u64 ffma2(u64 a, u64 b, u64 c) {
    u64 d;
    asm("fma.rn.f32x2 %0, %1, %2, %3;" : "=l"(d) : "l"(a), "l"(b), "l"(c));
    return d;
}
__device__ __forceinline__ u64 dup2(float v) {
    unsigned int u = __float_as_uint(v);
    return ((u64)u << 32) | (u64)u;
}

// ---------------------------------------------------------------------------
// K1: double LN on input. Block = 128 threads handles 128 voxels via smem tile.
// x is [c][voxel] (c-major). out g_norm is [voxel][c].
// ---------------------------------------------------------------------------
__global__ void __launch_bounds__(128) ln_in_kernel(
        const float* __restrict__ x,
        const float* __restrict__ lw, const float* __restrict__ lb,
        const float* __restrict__ mw, const float* __restrict__ mb,
        float* __restrict__ out) {
    __shared__ float s[128 * 132];
    __shared__ float slw[128], slb[128], smw[128], smb[128];
    int tid = threadIdx.x;
    int vBase = blockIdx.x << 7;
    slw[tid] = lw[tid]; slb[tid] = lb[tid];
    smw[tid] = mw[tid]; smb[tid] = mb[tid];
    #pragma unroll 8
    for (int i = tid; i < 128 * 128; i += 128) {
        int c = i >> 7, v = i & 127;
        s[c * 132 + v] = x[c * LQ + vBase + v];   // coalesced (v contiguous)
    }
    __syncthreads();
    int v = tid;
    float s1 = 0.f, s2 = 0.f;
    #pragma unroll 8
    for (int c = 0; c < 128; c++) { float t = s[c * 132 + v]; s1 += t; s2 += t * t; }
    float m = s1 * (1.f / 128.f);
    float var = s2 * (1.f / 128.f) - m * m;
    float rs = rsqrtf(var + 1e-6f);
    float t1 = 0.f, t2 = 0.f;
    #pragma unroll 8
    for (int c = 0; c < 128; c++) {
        float yy = (s[c * 132 + v] - m) * rs * slw[c] + slb[c];
        t1 += yy; t2 += yy * yy;
    }
    float m2 = t1 * (1.f / 128.f);
    float v2 = t2 * (1.f / 128.f) - m2 * m2;
    float rs2 = rsqrtf(v2 + 1e-5f);
    #pragma unroll 8
    for (int c = 0; c < 128; c++) {
        float yy = (s[c * 132 + v] - m) * rs * slw[c] + slb[c];
        s[c * 132 + v] = (yy - m2) * rs2 * smw[c] + smb[c];
    }
    __syncthreads();
    #pragma unroll 8
    for (int i = tid; i < 128 * 128; i += 128) {
        int vv = i >> 7, c = i & 127;
        out[(vBase + vv) * NC + c] = s[c * 132 + vv];  // coalesced (c contiguous)
    }
}

// K11: LN over rows of g_res (row-major [voxel][c]), eps 1e-6
__global__ void ln_row_kernel(const float* __restrict__ in,
                              const float* __restrict__ lw, const float* __restrict__ lb,
                              float* __restrict__ out) {
    int v = (blockIdx.x * blockDim.x + threadIdx.x) >> 5;
    int lane = threadIdx.x & 31;
    float vals[4]; float s1 = 0.f, s2 = 0.f;
    #pragma unroll
    for (int i = 0; i < 4; i++) {
        int c = lane + (i << 5);
        float t = in[v * NC + c];
        vals[i] = t; s1 += t; s2 += t * t;
    }
    s1 = wsum(s1); s2 = wsum(s2);
    float m = s1 * (1.f / 128.f);
    float var = s2 * (1.f / 128.f) - m * m;
    float rs = rsqrtf(var + 1e-6f);
    #pragma unroll
    for (int i = 0; i < 4; i++) {
        int c = lane + (i << 5);
        out[v * NC + c] = (vals[i] - m) * rs * lw[c] + lb[c];
    }
}

// ---------------------------------------------------------------------------
// FFMA2 GEMM:  C[M,N] = A[M,K] * W[N,K]^T,  BN=64, BK=16, microtile 8x4.
// BM template: 128 (256 thr) or 64 (128 thr). Double-buffered smem, B stored
// duplicated so packed f32x2 FMAs need no per-k packing.
// ---------------------------------------------------------------------------
struct ALoadDirect {
    const float* A; int K4;
    __device__ __forceinline__ float4 load(int row, int k4) const {
        return reinterpret_cast<const float4*>(A)[row * K4 + k4];
    }
};
struct ALoadNormGather {
    const float* A;
    __device__ __forceinline__ float4 load(int row, int k4) const {
        int r = row >> 12, l = row & 4095, v;
        if (r == 0)      v = l;
        else if (r == 1) v = ((l & 15) << 8) | (((l >> 8) & 15) << 4) | ((l >> 4) & 15);
        else             v = (((l >> 4) & 15) << 8) | ((l & 15) << 4) | ((l >> 8) & 15);
        return reinterpret_cast<const float4*>(A + (v << 7))[k4];
    }
};
struct ALoadCat {
    const float* Y;
    __device__ __forceinline__ float4 load(int row, int k4) const {
        int r = k4 >> 5, c4 = k4 & 31;
        return reinterpret_cast<const float4*>(Y + ((r << 12) + row) * NC)[c4];
    }
};

struct EpiStore {
    float* C; int stride;
    __device__ __forceinline__ void run(int row, int col, float v) const {
        C[row * stride + col] = v;
    }
};
struct EpiProjRes {
    float* res; const float* bias; const float* x;
    __device__ __forceinline__ void run(int row, int col, float v) const {
        res[row * NC + col] = v + bias[col] + x[(col << 12) + row];
    }
};
struct EpiBiasGelu {
    float* C; const float* bias;
    __device__ __forceinline__ void run(int row, int col, float v) const {
        float g = v + bias[col];
        C[row * 512 + col] = 0.5f * g * (1.0f + erff(g * 0.70710678118654752f));
    }
};
struct EpiFc2 {
    float* out; const float* bias; const float* res;
    __device__ __forceinline__ void run(int row, int col, float v) const {
        out[(col << 12) + row] = v + bias[col] + res[row * NC + col];
    }
};

template <int BM, class AL, class EP>
__global__ void __launch_bounds__(BM * 2) gemm2(AL al, const float* __restrict__ W,
                                                int N, int K, EP ep) {
    constexpr int NT = BM * 2;
    constexpr int AI = (BM * 4) / NT;   // float4 loads per thread for A tile
    constexpr int BI = 256 / NT;        // float4 loads per thread for B tile
    __shared__ float As[2][16][BM];
    __shared__ float Bsd[2][16][128];   // duplicated columns: [2c]==[2c+1]

    const int tid = threadIdx.x;
    const int tx = tid & 15, ty = tid >> 4;
    const int rowBase = blockIdx.y * BM;
    const int colBase = blockIdx.x << 6;

    u64 acc[4][4];
    #pragma unroll
    for (int i = 0; i < 4; i++)
        #pragma unroll
        for (int j = 0; j < 4; j++) acc[i][j] = 0ull;

    float4 pa[AI], pb[BI];

    auto loadG = [&](int kt) {
        #pragma unroll
        for (int ai = 0; ai < AI; ai++) {
            int i = tid + ai * NT;
            int r = i >> 2, q = i & 3;
            pa[ai] = al.load(rowBase + r, (kt >> 2) + q);
        }
        #pragma unroll
        for (int bi = 0; bi < BI; bi++) {
            int i = tid + bi * NT;
            int c = i >> 2, q = i & 3;
            int n = colBase + c;
            pb[bi] = (n < N)
                ? *reinterpret_cast<const float4*>(W + n * K + kt + (q << 2))
                : make_float4(0.f, 0.f, 0.f, 0.f);
        }
    };
    auto stsG = [&](int buf) {
        #pragma unroll
        for (int ai = 0; ai < AI; ai++) {
            int i = tid + ai * NT;
            int r = i >> 2, q = i & 3;
            As[buf][4 * q + 0][r] = pa[ai].x;
            As[buf][4 * q + 1][r] = pa[ai].y;
            As[buf][4 * q + 2][r] = pa[ai].z;
            As[buf][4 * q + 3][r] = pa[ai].w;
        }
        #pragma unroll
        for (int bi = 0; bi < BI; bi++) {
            int i = tid + bi * NT;
            int c = i >> 2, q = i & 3;
            u64* row0 = reinterpret_cast<u64*>(&Bsd[buf][4 * q + 0][2 * c]);
            u64* row1 = reinterpret_cast<u64*>(&Bsd[buf][4 * q + 1][2 * c]);
            u64* row2 = reinterpret_cast<u64*>(&Bsd[buf][4 * q + 2][2 * c]);
            u64* row3 = reinterpret_cast<u64*>(&Bsd[buf][4 * q + 3][2 * c]);
            *row0 = dup2(pb[bi].x);
            *row1 = dup2(pb[bi].y);
            *row2 = dup2(pb[bi].z);
            *row3 = dup2(pb[bi].w);
        }
    };

    loadG(0);
    stsG(0);
    __syncthreads();

    const int T = K >> 4;
    for (int t = 0; t < T; t++) {
        if (t + 1 < T) loadG((t + 1) << 4);
        int cur = t & 1;
        #pragma unroll
        for (int k = 0; k < 16; k++) {
            ulonglong2 a01 = *reinterpret_cast<const ulonglong2*>(&As[cur][k][ty << 3]);
            ulonglong2 a23 = *reinterpret_cast<const ulonglong2*>(&As[cur][k][(ty << 3) + 4]);
            ulonglong2 b01 = *reinterpret_cast<const ulonglong2*>(&Bsd[cur][k][tx << 3]);
            ulonglong2 b23 = *reinterpret_cast<const ulonglong2*>(&Bsd[cur][k][(tx << 3) + 4]);
            u64 av[4] = {a01.x, a01.y, a23.x, a23.y};
            u64 bv[4] = {b01.x, b01.y, b23.x, b23.y};
            #pragma unroll
            for (int ip = 0; ip < 4; ip++)
                #pragma unroll
                for (int j = 0; j < 4; j++)
                    acc[ip][j] = ffma2(av[ip], bv[j], acc[ip][j]);
        }
        if (t + 1 < T) {
            stsG(1 - cur);
            __syncthreads();
        }
    }

    #pragma unroll
    for (int ip = 0; ip < 4; ip++) {
        int row0 = rowBase + (ty << 3) + 2 * ip;
        #pragma unroll
        for (int j = 0; j < 4; j++) {
            int col = colBase + (tx << 2) + j;
            if (col < N) {
                float lo = __uint_as_float((unsigned int)acc[ip][j]);
                float hi = __uint_as_float((unsigned int)(acc[ip][j] >> 32));
                ep.run(row0, col, lo);
                ep.run(row0 + 1, col, hi);
            }
        }
    }
}

// ---------------------------------------------------------------------------
// K3: causal depthwise conv (D_CONV=4) + silu
// ---------------------------------------------------------------------------
__global__ void conv_kernel(const float* __restrict__ xz,
                            const float* __restrict__ cw, const float* __restrict__ cb,
                            float* __restrict__ xc) {
    int idx = blockIdx.x * 256 + threadIdx.x;
    int d = idx & 255;
    int rt = idx >> 8;
    int t = rt & 4095;
    float acc = cb[d];
    const float* base = xz + rt * 512 + d;
    #pragma unroll
    for (int k = 0; k < 4; k++) {
        int tt = t - 3 + k;
        if (tt >= 0) acc += cw[d * 4 + k] * base[(k - 3) * 512];
    }
    xc[idx] = acc / (1.0f + fast_exp(-acc));
}

// ---------------------------------------------------------------------------
// K5: dt_proj + softplus + precompute e1/du/silu(z)
// ---------------------------------------------------------------------------
__global__ void dt_kernel(const float* __restrict__ xdbl, const float* __restrict__ xc,
                          const float* __restrict__ xz,
                          const float* __restrict__ dtw, const float* __restrict__ dtb,
                          float* __restrict__ e1o, float* __restrict__ duo,
                          float* __restrict__ szo) {
    int row = blockIdx.x;
    int d = threadIdx.x;
    __shared__ float sdt[8];
    if (d < 8) sdt[d] = xdbl[row * 40 + d];
    __syncthreads();
    float acc = dtb[d];
    #pragma unroll
    for (int j = 0; j < 8; j++) acc += sdt[j] * dtw[d * 8 + j];
    float delta = softplusf_(acc);
    int o = row * DI + d;
    e1o[o] = fast_exp(-delta);
    duo[o] = delta * xc[o];
    float z = xz[row * 512 + 256 + d];
    szo[o] = z / (1.0f + fast_exp(-z));
}

// ---------------------------------------------------------------------------
// Chunked selective scan, 3 passes. dA_n = e1^(n+1) power-table fast path
// (A[d][n] == -(n+1)), generic fallback per thread.
// ---------------------------------------------------------------------------
__global__ void __launch_bounds__(256) scan1_kernel(const float* __restrict__ xdbl,
                                                    const float* __restrict__ e1g,
                                                    const float* __restrict__ dug,
                                                    const float* __restrict__ A_log,
                                                    float* __restrict__ Sg,
                                                    float* __restrict__ pg) {
    int bid = blockIdx.x;               // r*NCHUNK + chunk
    int r = bid / NCHUNK, chunk = bid % NCHUNK;
    int d = threadIdx.x;
    __shared__ float sB[CHUNK * DST];
    int rowBase = r * LQ + chunk * CHUNK;
    for (int i = d; i < CHUNK * DST; i += 256) {
        int st = i >> 4, n = i & 15;
        sB[i] = xdbl[(rowBase + st) * 40 + 8 + n];
    }
    bool fastok = true; float aRow[16];
    #pragma unroll
    for (int n = 0; n < 16; n++) {
        float a = fast_exp(A_log[d * 16 + n]);
        aRow[n] = -a;
        fastok = fastok && (fabsf(a - (float)(n + 1)) < 0.4f);
    }
    __syncthreads();
    float S[16];
    #pragma unroll
    for (int n = 0; n < 16; n++) S[n] = 0.f;
    float p = 1.f;
    const float* e1p = e1g + rowBase * DI + d;
    const float* dup = dug + rowBase * DI + d;
    if (fastok) {
        for (int st = 0; st < CHUNK; st++) {
            float e1 = e1p[st * DI], du = dup[st * DI];
            float e[17]; build_pows(e1, e);
            p *= e1;
            #pragma unroll
            for (int n = 0; n < 16; n++)
                S[n] = e[n + 1] * S[n] + du * sB[(st << 4) + n];
        }
    } else {
        for (int st = 0; st < CHUNK; st++) {
            float e1 = e1p[st * DI], du = dup[st * DI];
            float delta = -__logf(e1);
            p *= e1;
            #pragma unroll
            for (int n = 0; n < 16; n++)
                S[n] = fast_exp(aRow[n] * delta) * S[n] + du * sB[(st << 4) + n];
        }
    }
    int o = (bid * DI + d) * DST;
    #pragma unroll
    for (int n = 0; n < 16; n++) Sg[o + n] = S[n];
    pg[bid * DI + d] = p;
}

__global__ void scan2_kernel(const float* __restrict__ Sg, const float* __restrict__ pg,
                             const float* __restrict__ A_log, float* __restrict__ h0g) {
    int r = blockIdx.x;
    int d = threadIdx.x;
    bool fastok = true; float aRow[16];
    #pragma unroll
    for (int n = 0; n < 16; n++) {
        float a = fast_exp(A_log[d * 16 + n]);
        aRow[n] = -a;
        fastok = fastok && (fabsf(a - (float)(n + 1)) < 0.4f);
    }
    float H[16];
    #pragma unroll
    for (int n = 0; n < 16; n++) H[n] = 0.f;
    for (int c = 0; c < NCHUNK; c++) {
        int bid = r * NCHUNK + c;
        int o = (bid * DI + d) * DST;
        #pragma unroll
        for (int n = 0; n < 16; n++) h0g[o + n] = H[n];
        float p = pg[bid * DI + d];
        if (fastok) {
            float e[17]; build_pows(p, e);
            #pragma unroll
            for (int n = 0; n < 16; n++) H[n] = e[n + 1] * H[n] + Sg[o + n];
        } else {
            float lp = __logf(fmaxf(p, 1e-38f));
            #pragma unroll
            for (int n = 0; n < 16; n++)
                H[n] = fast_exp(aRow[n] * (-lp)) * H[n] + Sg[o + n];
        }
    }
}

__global__ void __launch_bounds__(256) scan3_kernel(const float* __restrict__ xdbl,
                                                    const float* __restrict__ e1g,
                                                    const float* __restrict__ dug,
                                                    const float* __restrict__ xcg,
                                                    const float* __restrict__ szg,
                                                    const float* __restrict__ A_log,
                                                    const float* __restrict__ Dp,
                                                    const float* __restrict__ h0g,
                                                    float* __restrict__ yg) {
    int bid = blockIdx.x;
    int r = bid / NCHUNK, chunk = bid % NCHUNK;
    int d = threadIdx.x;
    __shared__ float sB[CHUNK * DST];
    __shared__ float sC[CHUNK * DST];
    int rowBase = r * LQ + chunk * CHUNK;
    for (int i = d; i < CHUNK * DST; i += 256) {
        int st = i >> 4, n = i & 15;
        sB[i] = xdbl[(rowBase + st) * 40 + 8 + n];
        sC[i] = xdbl[(rowBase + st) * 40 + 24 + n];
    }
    bool fastok = true; float aRow[16];
    #pragma unroll
    for (int n = 0; n < 16; n++) {
        float a = fast_exp(A_log[d * 16 + n]);
        aRow[n] = -a;
        fastok = fastok && (fabsf(a - (float)(n + 1)) < 0.4f);
    }
    float h[16];
    {
        int o = (bid * DI + d) * DST;
        #pragma unroll
        for (int n = 0; n < 16; n++) h[n] = h0g[o + n];
    }
    float Dd = Dp[d];
    __syncthreads();
    const float* e1p = e1g + rowBase * DI + d;
    const float* dup = dug + rowBase * DI + d;
    const float* xcp = xcg + rowBase * DI + d;
    const float* szp = szg + rowBase * DI + d;
    float* yp = yg + rowBase * DI + d;
    if (fastok) {
        for (int st = 0; st < CHUNK; st++) {
            float e1 = e1p[st * DI], du = dup[st * DI];
            float u = xcp[st * DI], sz = szp[st * DI];
            float e[17]; build_pows(e1, e);
            float y0 = 0.f, y1 = 0.f, y2 = 0.f, y3 = 0.f;
            #pragma unroll
            for (int n = 0; n < 16; n++)
                h[n] = e[n + 1] * h[n] + du * sB[(st << 4) + n];
            #pragma unroll
            for (int n = 0; n < 16; n++) {
                float t = h[n] * sC[(st << 4) + n];
                if ((n & 3) == 0) y0 += t; else if ((n & 3) == 1) y1 += t;
                else if ((n & 3) == 2) y2 += t; else y3 += t;
            }
            float y = ((y0 + y1) + (y2 + y3)) + u * Dd;
            yp[st * DI] = y * sz;
        }
    } else {
        for (int st = 0; st < CHUNK; st++) {
            float e1 = e1p[st * DI], du = dup[st * DI];
            float u = xcp[st * DI], sz = szp[st * DI];
            float delta = -__logf(e1);
            float y = 0.f;
            #pragma unroll
            for (int n = 0; n < 16; n++) {
                h[n] = fast_exp(aRow[n] * delta) * h[n] + du * sB[(st << 4) + n];
                y += h[n] * sC[(st << 4) + n];
            }
            yp[st * DI] = (y + u * Dd) * sz;
        }
    }
}

// ---------------------------------------------------------------------------
// Host launch
// ---------------------------------------------------------------------------
extern "C" void kernel_launch(void* const* d_in, const int* in_sizes, int n_in,
                              void* d_out, int out_size) {
    const float* x        = (const float*)d_in[0];
    const float* ln_w     = (const float*)d_in[1];
    const float* ln_b     = (const float*)d_in[2];
    const float* mnorm_w  = (const float*)d_in[3];
    const float* mnorm_b  = (const float*)d_in[4];
    const float* in_proj_w= (const float*)d_in[5];
    const float* conv_w   = (const float*)d_in[6];
    const float* conv_b   = (const float*)d_in[7];
    const float* x_proj_w = (const float*)d_in[8];
    const float* dt_proj_w= (const float*)d_in[9];
    const float* dt_proj_b= (const float*)d_in[10];
    const float* A_log    = (const float*)d_in[11];
    const float* D_param  = (const float*)d_in[12];
    const float* out_proj_w=(const float*)d_in[13];
    const float* proj_w   = (const float*)d_in[14];
    const float* proj_b   = (const float*)d_in[15];
    const float* fc1_w    = (const float*)d_in[16];
    const float* fc1_b    = (const float*)d_in[17];
    const float* fc2_w    = (const float*)d_in[18];
    const float* fc2_b    = (const float*)d_in[19];

    float *norm, *xz, *xc, *xdbl, *e1, *du, *sz, *S, *p, *h0, *ygp, *y, *res, *hn, *fc1o;
    cudaGetSymbolAddress((void**)&norm, g_norm);
    cudaGetSymbolAddress((void**)&xz,   g_xz);
    cudaGetSymbolAddress((void**)&xc,   g_xc);
    cudaGetSymbolAddress((void**)&xdbl, g_xdbl);
    cudaGetSymbolAddress((void**)&e1,   g_e1);
    cudaGetSymbolAddress((void**)&du,   g_du);
    cudaGetSymbolAddress((void**)&sz,   g_sz);
    cudaGetSymbolAddress((void**)&S,    g_S);
    cudaGetSymbolAddress((void**)&p,    g_p);
    cudaGetSymbolAddress((void**)&h0,   g_h0);
    cudaGetSymbolAddress((void**)&ygp,  g_yg);
    cudaGetSymbolAddress((void**)&y,    g_y);
    cudaGetSymbolAddress((void**)&res,  g_res);
    cudaGetSymbolAddress((void**)&hn,   g_hn);
    cudaGetSymbolAddress((void**)&fc1o, g_fc1);

    // 1. double LN -> g_norm (coalesced tile version)
    ln_in_kernel<<<32, 128>>>(x, ln_w, ln_b, mnorm_w, mnorm_b, norm);
    // 2. in_proj: 12288 x 512 (K=128)
    gemm2<128><<<dim3(8, 96), 256>>>(ALoadNormGather{norm}, in_proj_w, 512, 128,
                                     EpiStore{xz, 512});
    // 3. causal conv + silu -> g_xc
    conv_kernel<<<NROW * DI / 256, 256>>>(xz, conv_w, conv_b, xc);
    // 4. x_proj: 12288 x 40 (K=256)
    gemm2<128><<<dim3(1, 96), 256>>>(ALoadDirect{xc, 64}, x_proj_w, 40, 256,
                                     EpiStore{xdbl, 40});
    // 5. dt_proj + softplus + precompute e1/du/silu(z)
    dt_kernel<<<NROW, 256>>>(xdbl, xc, xz, dt_proj_w, dt_proj_b, e1, du, sz);
    // 6-8. chunked selective scan (192 CTAs per scan pass)
    scan1_kernel<<<NSEQ * NCHUNK, 256>>>(xdbl, e1, du, A_log, S, p);
    scan2_kernel<<<NSEQ, 256>>>(S, p, A_log, h0);
    scan3_kernel<<<NSEQ * NCHUNK, 256>>>(xdbl, e1, du, xc, sz, A_log, D_param, h0, ygp);
    // 9. out_proj: 12288 x 128 (K=256)
    gemm2<128><<<dim3(2, 96), 256>>>(ALoadDirect{ygp, 64}, out_proj_w, 128, 256,
                                     EpiStore{y, 128});
    // 10. proj + bias + x residual: 4096 x 128 (K=384)
    gemm2<64><<<dim3(2, 64), 128>>>(ALoadCat{y}, proj_w, 128, 384,
                                    EpiProjRes{res, proj_b, x});
    // 11. LN(res) -> g_hn
    ln_row_kernel<<<512, 256>>>(res, ln_w, ln_b, hn);
    // 12. fc1 + bias + gelu: 4096 x 512 (K=128)
    gemm2<64><<<dim3(8, 64), 128>>>(ALoadDirect{hn, 32}, fc1_w, 512, 128,
                                    EpiBiasGelu{fc1o, fc1_b});
    // 13. fc2 + bias + residual, channel-major output: 4096 x 128 (K=512)
    gemm2<64><<<dim3(2, 64), 128>>>(ALoadDirect{fc1o, 128}, fc2_w, 128, 512,
                                    EpiFc2{(float*)d_out, fc2_b, res});
    (void)in_sizes; (void)n_in; (void)out_size;
}

// round 6
// speedup vs baseline: 1.4290x; 1.4290x over previous
#include <cuda_runtime.h>
#include <cuda_bf16.h>
#include <math.h>

// ---------------------------------------------------------------------------
// Problem dims
// ---------------------------------------------------------------------------
#define LQ   4096            // L = 16*16*16
#define NC   128             // channels C
#define DI   256             // D_INNER
#define NSEQ 3               // directions
#define NROW (NSEQ*LQ)       // 12288
#define DST  16              // D_STATE
#define NCHUNK 64            // chunks per sequence
#define CHUNK  64            // chunk length

// ---------------------------------------------------------------------------
// Workspace (static device arrays — no cudaMalloc anywhere)
// ---------------------------------------------------------------------------
__device__ float g_norm[LQ * NC];
__device__ float g_xz  [NROW * 512];
__device__ float g_xc  [NROW * DI];
__device__ float g_xdbl[NROW * 40];
__device__ float g_e1  [NROW * DI];
__device__ float g_du  [NROW * DI];
__device__ float g_sz  [NROW * DI];
__device__ float g_S   [NSEQ * NCHUNK * DI * DST];
__device__ float g_p   [NSEQ * NCHUNK * DI];
__device__ float g_h0  [NSEQ * NCHUNK * DI * DST];
__device__ float g_yg  [NROW * DI];
__device__ float g_y   [NROW * NC];
__device__ float g_res [LQ * NC];
__device__ float g_hn  [LQ * NC];
__device__ float g_fc1 [LQ * 512];

// ---------------------------------------------------------------------------
// Helpers
// ---------------------------------------------------------------------------
__device__ __forceinline__ float fast_exp(float x) {
    x = fminf(fmaxf(x, -87.0f), 87.0f);
    float t = x * 1.4426950408889634f;
    float n = rintf(t);
    float f = t - n;
    float g = f * 0.6931471805599453f;
    float p = 1.0f + g * (1.0f + g * (0.5f + g * (0.16666667f + g * (0.041666668f +
              g * (0.008333334f + g * 0.0013888889f)))));
    float s = __int_as_float(((int)n + 127) << 23);
    return p * s;
}

__device__ __forceinline__ float softplusf_(float x) {
    if (x > 15.0f) return x;
    float y = fast_exp(x);
    if (y < 0.05f) {
        return y * (1.0f + y * (-0.5f + y * (0.33333334f + y * (-0.25f + y * 0.2f))));
    }
    return log1pf(y);
}

__device__ __forceinline__ float wsum(float v) {
    #pragma unroll
    for (int o = 16; o > 0; o >>= 1) v += __shfl_xor_sync(0xffffffffu, v, o);
    return v;
}

__device__ __forceinline__ void build_pows(float e1, float* e) {
    e[0] = 1.0f; e[1] = e1;
    #pragma unroll
    for (int j = 2; j <= 16; j++) e[j] = e[j >> 1] * e[j - (j >> 1)];
}

// bf16 hi/lo split of a float2 (k-pair) into packed bf16x2 registers.
__device__ __forceinline__ void split2(float2 v, unsigned& hi, unsigned& lo) {
    __nv_bfloat162 h = __floats2bfloat162_rn(v.x, v.y);
    float r0 = v.x - __low2float(h);
    float r1 = v.y - __high2float(h);
    __nv_bfloat162 l = __floats2bfloat162_rn(r0, r1);
    hi = *reinterpret_cast<unsigned*>(&h);
    lo = *reinterpret_cast<unsigned*>(&l);
}

// m16n8k16 bf16 mma, fp32 accumulate
__device__ __forceinline__ void mma16816(float c[4], const unsigned a[4], const unsigned b[2]) {
    asm volatile("mma.sync.aligned.m16n8k16.row.col.f32.bf16.bf16.f32 "
        "{%0,%1,%2,%3}, {%4,%5,%6,%7}, {%8,%9}, {%0,%1,%2,%3};"
        : "+f"(c[0]), "+f"(c[1]), "+f"(c[2]), "+f"(c[3])
        : "r"(a[0]), "r"(a[1]), "r"(a[2]), "r"(a[3]), "r"(b[0]), "r"(b[1]));
}

// ---------------------------------------------------------------------------
// K1: double LN on input (smem transpose tile). x is [c][voxel]; out [voxel][c]
// ---------------------------------------------------------------------------
__global__ void __launch_bounds__(128) ln_in_kernel(
        const float* __restrict__ x,
        const float* __restrict__ lw, const float* __restrict__ lb,
        const float* __restrict__ mw, const float* __restrict__ mb,
        float* __restrict__ out) {
    __shared__ float s[128 * 132];
    __shared__ float slw[128], slb[128], smw[128], smb[128];
    int tid = threadIdx.x;
    int vBase = blockIdx.x << 7;
    slw[tid] = lw[tid]; slb[tid] = lb[tid];
    smw[tid] = mw[tid]; smb[tid] = mb[tid];
    #pragma unroll 8
    for (int i = tid; i < 128 * 128; i += 128) {
        int c = i >> 7, v = i & 127;
        s[c * 132 + v] = x[c * LQ + vBase + v];
    }
    __syncthreads();
    int v = tid;
    float s1 = 0.f, s2 = 0.f;
    #pragma unroll 8
    for (int c = 0; c < 128; c++) { float t = s[c * 132 + v]; s1 += t; s2 += t * t; }
    float m = s1 * (1.f / 128.f);
    float var = s2 * (1.f / 128.f) - m * m;
    float rs = rsqrtf(var + 1e-6f);
    float t1 = 0.f, t2 = 0.f;
    #pragma unroll 8
    for (int c = 0; c < 128; c++) {
        float yy = (s[c * 132 + v] - m) * rs * slw[c] + slb[c];
        t1 += yy; t2 += yy * yy;
    }
    float m2 = t1 * (1.f / 128.f);
    float v2 = t2 * (1.f / 128.f) - m2 * m2;
    float rs2 = rsqrtf(v2 + 1e-5f);
    #pragma unroll 8
    for (int c = 0; c < 128; c++) {
        float yy = (s[c * 132 + v] - m) * rs * slw[c] + slb[c];
        s[c * 132 + v] = (yy - m2) * rs2 * smw[c] + smb[c];
    }
    __syncthreads();
    #pragma unroll 8
    for (int i = tid; i < 128 * 128; i += 128) {
        int vv = i >> 7, c = i & 127;
        out[(vBase + vv) * NC + c] = s[c * 132 + vv];
    }
}

// K11: LN over rows of g_res (row-major [voxel][c]), eps 1e-6
__global__ void ln_row_kernel(const float* __restrict__ in,
                              const float* __restrict__ lw, const float* __restrict__ lb,
                              float* __restrict__ out) {
    int v = (blockIdx.x * blockDim.x + threadIdx.x) >> 5;
    int lane = threadIdx.x & 31;
    float vals[4]; float s1 = 0.f, s2 = 0.f;
    #pragma unroll
    for (int i = 0; i < 4; i++) {
        int c = lane + (i << 5);
        float t = in[v * NC + c];
        vals[i] = t; s1 += t; s2 += t * t;
    }
    s1 = wsum(s1); s2 = wsum(s2);
    float m = s1 * (1.f / 128.f);
    float var = s2 * (1.f / 128.f) - m * m;
    float rs = rsqrtf(var + 1e-6f);
    #pragma unroll
    for (int i = 0; i < 4; i++) {
        int c = lane + (i << 5);
        out[v * NC + c] = (vals[i] - m) * rs * lw[c] + lb[c];
    }
}

// ---------------------------------------------------------------------------
// Tensor-core GEMM (bf16 3-term split, fp32-accurate):
// C[M,N] = A[M,K] * W[N,K]^T. BM in {128, 64}, BN=64, BK=32.
// 2 warps along N, BM/32 warps along M; each warp computes 32x32 via
// m16n8k16 mma. A via loader functor, epilogue fused.
// ---------------------------------------------------------------------------
struct ALoadDirect {
    const float* A; int K4;
    __device__ __forceinline__ float4 load(int row, int k4) const {
        return reinterpret_cast<const float4*>(A)[row * K4 + k4];
    }
};
struct ALoadNormGather {
    const float* A;
    __device__ __forceinline__ float4 load(int row, int k4) const {
        int r = row >> 12, l = row & 4095, v;
        if (r == 0)      v = l;
        else if (r == 1) v = ((l & 15) << 8) | (((l >> 8) & 15) << 4) | ((l >> 4) & 15);
        else             v = (((l >> 4) & 15) << 8) | ((l & 15) << 4) | ((l >> 8) & 15);
        return reinterpret_cast<const float4*>(A + (v << 7))[k4];
    }
};
struct ALoadCat {
    const float* Y;
    __device__ __forceinline__ float4 load(int row, int k4) const {
        int r = k4 >> 5, c4 = k4 & 31;
        return reinterpret_cast<const float4*>(Y + ((r << 12) + row) * NC)[c4];
    }
};

struct EpiStore {
    float* C; int stride;
    __device__ __forceinline__ void run(int row, int col, float v) const {
        C[row * stride + col] = v;
    }
};
struct EpiProjRes {
    float* res; const float* bias; const float* x;
    __device__ __forceinline__ void run(int row, int col, float v) const {
        res[row * NC + col] = v + bias[col] + x[(col << 12) + row];
    }
};
struct EpiBiasGelu {
    float* C; const float* bias;
    __device__ __forceinline__ void run(int row, int col, float v) const {
        float g = v + bias[col];
        C[row * 512 + col] = 0.5f * g * (1.0f + erff(g * 0.70710678118654752f));
    }
};
struct EpiFc2 {
    float* out; const float* bias; const float* res;
    __device__ __forceinline__ void run(int row, int col, float v) const {
        out[(col << 12) + row] = v + bias[col] + res[row * NC + col];
    }
};

template <int BM, class AL, class EP>
__global__ void __launch_bounds__(BM * 2) gemm_mma(AL al, const float* __restrict__ W,
                                                   int N, int K, EP ep) {
    constexpr int NT = BM * 2;          // threads (warps = NT/32)
    constexpr int MW = BM / 32;         // warps along M
    constexpr int AI = BM * 8 / NT;     // float4 A loads/thread per chunk (=4)
    constexpr int BI = 512 / NT;        // float4 B loads/thread per chunk
    __shared__ float As[BM][40];
    __shared__ float Bs[64][40];

    const int tid = threadIdx.x, wid = tid >> 5, lane = tid & 31;
    const int g = lane >> 2, q = lane & 3;
    const int wm = wid % MW, wn = wid / MW;
    const int rowBase = blockIdx.y * BM;
    const int colBase = blockIdx.x << 6;

    float4 pa[AI], pb[BI];
    float acc[2][4][4] = {};

    auto loadG = [&](int kt4) {
        #pragma unroll
        for (int ai = 0; ai < AI; ai++) {
            int i = tid + ai * NT; int r = i >> 3, c4 = i & 7;
            pa[ai] = al.load(rowBase + r, kt4 + c4);
        }
        #pragma unroll
        for (int bi = 0; bi < BI; bi++) {
            int i = tid + bi * NT; int n = i >> 3, c4 = i & 7;
            int col = colBase + n;
            pb[bi] = (col < N)
                ? *reinterpret_cast<const float4*>(W + (size_t)col * K + (kt4 + c4) * 4)
                : make_float4(0.f, 0.f, 0.f, 0.f);
        }
    };
    auto sts = [&]() {
        #pragma unroll
        for (int ai = 0; ai < AI; ai++) {
            int i = tid + ai * NT; int r = i >> 3, c4 = i & 7;
            *reinterpret_cast<float4*>(&As[r][c4 << 2]) = pa[ai];
        }
        #pragma unroll
        for (int bi = 0; bi < BI; bi++) {
            int i = tid + bi * NT; int n = i >> 3, c4 = i & 7;
            *reinterpret_cast<float4*>(&Bs[n][c4 << 2]) = pb[bi];
        }
    };

    loadG(0); sts(); __syncthreads();
    const int T = K >> 5;
    for (int t = 0; t < T; t++) {
        if (t + 1 < T) loadG((t + 1) << 3);
        #pragma unroll
        for (int ks = 0; ks < 32; ks += 16) {
            unsigned bh[4][2], bl[4][2];
            #pragma unroll
            for (int nt = 0; nt < 4; nt++) {
                int col = wn * 32 + nt * 8 + g;
                float2 v0 = *reinterpret_cast<const float2*>(&Bs[col][ks + 2 * q]);
                float2 v1 = *reinterpret_cast<const float2*>(&Bs[col][ks + 2 * q + 8]);
                split2(v0, bh[nt][0], bl[nt][0]);
                split2(v1, bh[nt][1], bl[nt][1]);
            }
            #pragma unroll
            for (int mt = 0; mt < 2; mt++) {
                int row = wm * 32 + mt * 16 + g;
                unsigned ah[4], alo[4];
                float2 u0 = *reinterpret_cast<const float2*>(&As[row][ks + 2 * q]);
                float2 u1 = *reinterpret_cast<const float2*>(&As[row + 8][ks + 2 * q]);
                float2 u2 = *reinterpret_cast<const float2*>(&As[row][ks + 2 * q + 8]);
                float2 u3 = *reinterpret_cast<const float2*>(&As[row + 8][ks + 2 * q + 8]);
                split2(u0, ah[0], alo[0]); split2(u1, ah[1], alo[1]);
                split2(u2, ah[2], alo[2]); split2(u3, ah[3], alo[3]);
                #pragma unroll
                for (int nt = 0; nt < 4; nt++) {
                    mma16816(acc[mt][nt], ah, bh[nt]);
                    mma16816(acc[mt][nt], ah, bl[nt]);
                    mma16816(acc[mt][nt], alo, bh[nt]);
                }
            }
        }
        __syncthreads();
        if (t + 1 < T) { sts(); __syncthreads(); }
    }

    #pragma unroll
    for (int mt = 0; mt < 2; mt++) {
        int row = rowBase + wm * 32 + mt * 16 + g;
        #pragma unroll
        for (int nt = 0; nt < 4; nt++) {
            int col = colBase + wn * 32 + nt * 8 + 2 * q;
            if (col < N) {
                ep.run(row, col, acc[mt][nt][0]);
                ep.run(row + 8, col, acc[mt][nt][2]);
                if (col + 1 < N) {
                    ep.run(row, col + 1, acc[mt][nt][1]);
                    ep.run(row + 8, col + 1, acc[mt][nt][3]);
                }
            }
        }
    }
}

// ---------------------------------------------------------------------------
// K3: causal depthwise conv (D_CONV=4) + silu
// ---------------------------------------------------------------------------
__global__ void conv_kernel(const float* __restrict__ xz,
                            const float* __restrict__ cw, const float* __restrict__ cb,
                            float* __restrict__ xc) {
    int idx = blockIdx.x * 256 + threadIdx.x;
    int d = idx & 255;
    int rt = idx >> 8;
    int t = rt & 4095;
    float acc = cb[d];
    const float* base = xz + rt * 512 + d;
    #pragma unroll
    for (int k = 0; k < 4; k++) {
        int tt = t - 3 + k;
        if (tt >= 0) acc += cw[d * 4 + k] * base[(k - 3) * 512];
    }
    xc[idx] = acc / (1.0f + fast_exp(-acc));
}

// ---------------------------------------------------------------------------
// K5: dt_proj + softplus + precompute e1/du/silu(z)
// ---------------------------------------------------------------------------
__global__ void dt_kernel(const float* __restrict__ xdbl, const float* __restrict__ xc,
                          const float* __restrict__ xz,
                          const float* __restrict__ dtw, const float* __restrict__ dtb,
                          float* __restrict__ e1o, float* __restrict__ duo,
                          float* __restrict__ szo) {
    int row = blockIdx.x;
    int d = threadIdx.x;
    __shared__ float sdt[8];
    if (d < 8) sdt[d] = xdbl[row * 40 + d];
    __syncthreads();
    float acc = dtb[d];
    #pragma unroll
    for (int j = 0; j < 8; j++) acc += sdt[j] * dtw[d * 8 + j];
    float delta = softplusf_(acc);
    int o = row * DI + d;
    e1o[o] = fast_exp(-delta);
    duo[o] = delta * xc[o];
    float z = xz[row * 512 + 256 + d];
    szo[o] = z / (1.0f + fast_exp(-z));
}

// ---------------------------------------------------------------------------
// Chunked selective scan, 3 passes
// ---------------------------------------------------------------------------
__global__ void __launch_bounds__(256) scan1_kernel(const float* __restrict__ xdbl,
                                                    const float* __restrict__ e1g,
                                                    const float* __restrict__ dug,
                                                    const float* __restrict__ A_log,
                                                    float* __restrict__ Sg,
                                                    float* __restrict__ pg) {
    int bid = blockIdx.x;
    int r = bid / NCHUNK, chunk = bid % NCHUNK;
    int d = threadIdx.x;
    __shared__ float sB[CHUNK * DST];
    int rowBase = r * LQ + chunk * CHUNK;
    for (int i = d; i < CHUNK * DST; i += 256) {
        int st = i >> 4, n = i & 15;
        sB[i] = xdbl[(rowBase + st) * 40 + 8 + n];
    }
    bool fastok = true; float aRow[16];
    #pragma unroll
    for (int n = 0; n < 16; n++) {
        float a = fast_exp(A_log[d * 16 + n]);
        aRow[n] = -a;
        fastok = fastok && (fabsf(a - (float)(n + 1)) < 0.4f);
    }
    __syncthreads();
    float S[16];
    #pragma unroll
    for (int n = 0; n < 16; n++) S[n] = 0.f;
    float p = 1.f;
    const float* e1p = e1g + rowBase * DI + d;
    const float* dup = dug + rowBase * DI + d;
    if (fastok) {
        for (int st = 0; st < CHUNK; st++) {
            float e1 = e1p[st * DI], du = dup[st * DI];
            float e[17]; build_pows(e1, e);
            p *= e1;
            #pragma unroll
            for (int n = 0; n < 16; n++)
                S[n] = e[n + 1] * S[n] + du * sB[(st << 4) + n];
        }
    } else {
        for (int st = 0; st < CHUNK; st++) {
            float e1 = e1p[st * DI], du = dup[st * DI];
            float delta = -__logf(e1);
            p *= e1;
            #pragma unroll
            for (int n = 0; n < 16; n++)
                S[n] = fast_exp(aRow[n] * delta) * S[n] + du * sB[(st << 4) + n];
        }
    }
    int o = (bid * DI + d) * DST;
    #pragma unroll
    for (int n = 0; n < 16; n++) Sg[o + n] = S[n];
    pg[bid * DI + d] = p;
}

__global__ void scan2_kernel(const float* __restrict__ Sg, const float* __restrict__ pg,
                             const float* __restrict__ A_log, float* __restrict__ h0g) {
    int r = blockIdx.x;
    int d = threadIdx.x;
    bool fastok = true; float aRow[16];
    #pragma unroll
    for (int n = 0; n < 16; n++) {
        float a = fast_exp(A_log[d * 16 + n]);
        aRow[n] = -a;
        fastok = fastok && (fabsf(a - (float)(n + 1)) < 0.4f);
    }
    float H[16];
    #pragma unroll
    for (int n = 0; n < 16; n++) H[n] = 0.f;
    for (int c = 0; c < NCHUNK; c++) {
        int bid = r * NCHUNK + c;
        int o = (bid * DI + d) * DST;
        #pragma unroll
        for (int n = 0; n < 16; n++) h0g[o + n] = H[n];
        float p = pg[bid * DI + d];
        if (fastok) {
            float e[17]; build_pows(p, e);
            #pragma unroll
            for (int n = 0; n < 16; n++) H[n] = e[n + 1] * H[n] + Sg[o + n];
        } else {
            float lp = __logf(fmaxf(p, 1e-38f));
            #pragma unroll
            for (int n = 0; n < 16; n++)
                H[n] = fast_exp(aRow[n] * (-lp)) * H[n] + Sg[o + n];
        }
    }
}

__global__ void __launch_bounds__(256) scan3_kernel(const float* __restrict__ xdbl,
                                                    const float* __restrict__ e1g,
                                                    const float* __restrict__ dug,
                                                    const float* __restrict__ xcg,
                                                    const float* __restrict__ szg,
                                                    const float* __restrict__ A_log,
                                                    const float* __restrict__ Dp,
                                                    const float* __restrict__ h0g,
                                                    float* __restrict__ yg) {
    int bid = blockIdx.x;
    int r = bid / NCHUNK, chunk = bid % NCHUNK;
    int d = threadIdx.x;
    __shared__ float sB[CHUNK * DST];
    __shared__ float sC[CHUNK * DST];
    int rowBase = r * LQ + chunk * CHUNK;
    for (int i = d; i < CHUNK * DST; i += 256) {
        int st = i >> 4, n = i & 15;
        sB[i] = xdbl[(rowBase + st) * 40 + 8 + n];
        sC[i] = xdbl[(rowBase + st) * 40 + 24 + n];
    }
    bool fastok = true; float aRow[16];
    #pragma unroll
    for (int n = 0; n < 16; n++) {
        float a = fast_exp(A_log[d * 16 + n]);
        aRow[n] = -a;
        fastok = fastok && (fabsf(a - (float)(n + 1)) < 0.4f);
    }
    float h[16];
    {
        int o = (bid * DI + d) * DST;
        #pragma unroll
        for (int n = 0; n < 16; n++) h[n] = h0g[o + n];
    }
    float Dd = Dp[d];
    __syncthreads();
    const float* e1p = e1g + rowBase * DI + d;
    const float* dup = dug + rowBase * DI + d;
    const float* xcp = xcg + rowBase * DI + d;
    const float* szp = szg + rowBase * DI + d;
    float* yp = yg + rowBase * DI + d;
    if (fastok) {
        for (int st = 0; st < CHUNK; st++) {
            float e1 = e1p[st * DI], du = dup[st * DI];
            float u = xcp[st * DI], sz = szp[st * DI];
            float e[17]; build_pows(e1, e);
            float y0 = 0.f, y1 = 0.f, y2 = 0.f, y3 = 0.f;
            #pragma unroll
            for (int n = 0; n < 16; n++)
                h[n] = e[n + 1] * h[n] + du * sB[(st << 4) + n];
            #pragma unroll
            for (int n = 0; n < 16; n++) {
                float t = h[n] * sC[(st << 4) + n];
                if ((n & 3) == 0) y0 += t; else if ((n & 3) == 1) y1 += t;
                else if ((n & 3) == 2) y2 += t; else y3 += t;
            }
            float y = ((y0 + y1) + (y2 + y3)) + u * Dd;
            yp[st * DI] = y * sz;
        }
    } else {
        for (int st = 0; st < CHUNK; st++) {
            float e1 = e1p[st * DI], du = dup[st * DI];
            float u = xcp[st * DI], sz = szp[st * DI];
            float delta = -__logf(e1);
            float y = 0.f;
            #pragma unroll
            for (int n = 0; n < 16; n++) {
                h[n] = fast_exp(aRow[n] * delta) * h[n] + du * sB[(st << 4) + n];
                y += h[n] * sC[(st << 4) + n];
            }
            yp[st * DI] = (y + u * Dd) * sz;
        }
    }
}

// ---------------------------------------------------------------------------
// Host launch
// ---------------------------------------------------------------------------
extern "C" void kernel_launch(void* const* d_in, const int* in_sizes, int n_in,
                              void* d_out, int out_size) {
    const float* x        = (const float*)d_in[0];
    const float* ln_w     = (const float*)d_in[1];
    const float* ln_b     = (const float*)d_in[2];
    const float* mnorm_w  = (const float*)d_in[3];
    const float* mnorm_b  = (const float*)d_in[4];
    const float* in_proj_w= (const float*)d_in[5];
    const float* conv_w   = (const float*)d_in[6];
    const float* conv_b   = (const float*)d_in[7];
    const float* x_proj_w = (const float*)d_in[8];
    const float* dt_proj_w= (const float*)d_in[9];
    const float* dt_proj_b= (const float*)d_in[10];
    const float* A_log    = (const float*)d_in[11];
    const float* D_param  = (const float*)d_in[12];
    const float* out_proj_w=(const float*)d_in[13];
    const float* proj_w   = (const float*)d_in[14];
    const float* proj_b   = (const float*)d_in[15];
    const float* fc1_w    = (const float*)d_in[16];
    const float* fc1_b    = (const float*)d_in[17];
    const float* fc2_w    = (const float*)d_in[18];
    const float* fc2_b    = (const float*)d_in[19];

    float *norm, *xz, *xc, *xdbl, *e1, *du, *sz, *S, *p, *h0, *ygp, *y, *res, *hn, *fc1o;
    cudaGetSymbolAddress((void**)&norm, g_norm);
    cudaGetSymbolAddress((void**)&xz,   g_xz);
    cudaGetSymbolAddress((void**)&xc,   g_xc);
    cudaGetSymbolAddress((void**)&xdbl, g_xdbl);
    cudaGetSymbolAddress((void**)&e1,   g_e1);
    cudaGetSymbolAddress((void**)&du,   g_du);
    cudaGetSymbolAddress((void**)&sz,   g_sz);
    cudaGetSymbolAddress((void**)&S,    g_S);
    cudaGetSymbolAddress((void**)&p,    g_p);
    cudaGetSymbolAddress((void**)&h0,   g_h0);
    cudaGetSymbolAddress((void**)&ygp,  g_yg);
    cudaGetSymbolAddress((void**)&y,    g_y);
    cudaGetSymbolAddress((void**)&res,  g_res);
    cudaGetSymbolAddress((void**)&hn,   g_hn);
    cudaGetSymbolAddress((void**)&fc1o, g_fc1);

    // 1. double LN -> g_norm
    ln_in_kernel<<<32, 128>>>(x, ln_w, ln_b, mnorm_w, mnorm_b, norm);
    // 2. in_proj: 12288 x 512 (K=128)
    gemm_mma<128><<<dim3(8, 96), 256>>>(ALoadNormGather{norm}, in_proj_w, 512, 128,
                                        EpiStore{xz, 512});
    // 3. causal conv + silu -> g_xc
    conv_kernel<<<NROW * DI / 256, 256>>>(xz, conv_w, conv_b, xc);
    // 4. x_proj: 12288 x 40 (K=256)
    gemm_mma<128><<<dim3(1, 96), 256>>>(ALoadDirect{xc, 64}, x_proj_w, 40, 256,
                                        EpiStore{xdbl, 40});
    // 5. dt_proj + softplus + precompute e1/du/silu(z)
    dt_kernel<<<NROW, 256>>>(xdbl, xc, xz, dt_proj_w, dt_proj_b, e1, du, sz);
    // 6-8. chunked selective scan
    scan1_kernel<<<NSEQ * NCHUNK, 256>>>(xdbl, e1, du, A_log, S, p);
    scan2_kernel<<<NSEQ, 256>>>(S, p, A_log, h0);
    scan3_kernel<<<NSEQ * NCHUNK, 256>>>(xdbl, e1, du, xc, sz, A_log, D_param, h0, ygp);
    // 9. out_proj: 12288 x 128 (K=256)
    gemm_mma<128><<<dim3(2, 96), 256>>>(ALoadDirect{ygp, 64}, out_proj_w, 128, 256,
                                        EpiStore{y, 128});
    // 10. proj + bias + x residual: 4096 x 128 (K=384)
    gemm_mma<64><<<dim3(2, 64), 128>>>(ALoadCat{y}, proj_w, 128, 384,
                                       EpiProjRes{res, proj_b, x});
    // 11. LN(res) -> g_hn
    ln_row_kernel<<<512, 256>>>(res, ln_w, ln_b, hn);
    // 12. fc1 + bias + gelu: 4096 x 512 (K=128)
    gemm_mma<128><<<dim3(8, 32), 256>>>(ALoadDirect{hn, 32}, fc1_w, 512, 128,
                                        EpiBiasGelu{fc1o, fc1_b});
    // 13. fc2 + bias + residual, channel-major output: 4096 x 128 (K=512)
    gemm_mma<64><<<dim3(2, 64), 128>>>(ALoadDirect{fc1o, 128}, fc2_w, 128, 512,
                                       EpiFc2{(float*)d_out, fc2_b, res});
    (void)in_sizes; (void)n_in; (void)out_size;
}

// round 8
// speedup vs baseline: 2.4143x; 1.6895x over previous
#include <cuda_runtime.h>
#include <cuda_bf16.h>
#include <math.h>

// ---------------------------------------------------------------------------
// Problem dims
// ---------------------------------------------------------------------------
#define LQ   4096            // L = 16*16*16
#define NC   128             // channels C
#define DI   256             // D_INNER
#define NSEQ 3               // directions
#define NROW (NSEQ*LQ)       // 12288
#define DST  16              // D_STATE
#define NCHUNK 64            // chunks per sequence
#define CHUNK  64            // chunk length

// ---------------------------------------------------------------------------
// Workspace (static device arrays — no cudaMalloc anywhere)
// ---------------------------------------------------------------------------
__device__ float g_norm[LQ * NC];
__device__ float g_xz  [NROW * 512];
__device__ float g_xc  [NROW * DI];
__device__ float g_xdbl[NROW * 40];
__device__ float g_e1  [NROW * DI];
__device__ float g_du  [NROW * DI];
__device__ float g_sz  [NROW * DI];
__device__ float g_S   [NSEQ * NCHUNK * DI * DST];
__device__ float g_p   [NSEQ * NCHUNK * DI];
__device__ float g_h0  [NSEQ * NCHUNK * DI * DST];
__device__ float g_yg  [NROW * DI];
__device__ float g_y   [NROW * NC];
__device__ float g_res [LQ * NC];
__device__ float g_hn  [LQ * NC];
__device__ float g_fc1 [LQ * 512];

// ---------------------------------------------------------------------------
// Helpers
// ---------------------------------------------------------------------------
__device__ __forceinline__ float fast_exp(float x) {
    x = fminf(fmaxf(x, -87.0f), 87.0f);
    float t = x * 1.4426950408889634f;
    float n = rintf(t);
    float f = t - n;
    float g = f * 0.6931471805599453f;
    float p = 1.0f + g * (1.0f + g * (0.5f + g * (0.16666667f + g * (0.041666668f +
              g * (0.008333334f + g * 0.0013888889f)))));
    float s = __int_as_float(((int)n + 127) << 23);
    return p * s;
}

__device__ __forceinline__ float softplusf_(float x) {
    if (x > 15.0f) return x;
    float y = fast_exp(x);
    if (y < 0.05f) {
        return y * (1.0f + y * (-0.5f + y * (0.33333334f + y * (-0.25f + y * 0.2f))));
    }
    return log1pf(y);
}

__device__ __forceinline__ float wsum(float v) {
    #pragma unroll
    for (int o = 16; o > 0; o >>= 1) v += __shfl_xor_sync(0xffffffffu, v, o);
    return v;
}

__device__ __forceinline__ void build_pows(float e1, float* e) {
    e[0] = 1.0f; e[1] = e1;
    #pragma unroll
    for (int j = 2; j <= 16; j++) e[j] = e[j >> 1] * e[j - (j >> 1)];
}

// m16n8k16 bf16 mma, fp32 accumulate
__device__ __forceinline__ void mma16816(float c[4], const unsigned a[4], const unsigned b[2]) {
    asm volatile("mma.sync.aligned.m16n8k16.row.col.f32.bf16.bf16.f32 "
        "{%0,%1,%2,%3}, {%4,%5,%6,%7}, {%8,%9}, {%0,%1,%2,%3};"
        : "+f"(c[0]), "+f"(c[1]), "+f"(c[2]), "+f"(c[3])
        : "r"(a[0]), "r"(a[1]), "r"(a[2]), "r"(a[3]), "r"(b[0]), "r"(b[1]));
}

// split a float4 into packed bf16x2 hi and lo pairs (2 uints each)
__device__ __forceinline__ void split4(float4 v, uint2& hi, uint2& lo) {
    __nv_bfloat162 h01 = __floats2bfloat162_rn(v.x, v.y);
    __nv_bfloat162 h23 = __floats2bfloat162_rn(v.z, v.w);
    float r0 = v.x - __low2float(h01);
    float r1 = v.y - __high2float(h01);
    float r2 = v.z - __low2float(h23);
    float r3 = v.w - __high2float(h23);
    __nv_bfloat162 l01 = __floats2bfloat162_rn(r0, r1);
    __nv_bfloat162 l23 = __floats2bfloat162_rn(r2, r3);
    hi.x = *reinterpret_cast<unsigned*>(&h01);
    hi.y = *reinterpret_cast<unsigned*>(&h23);
    lo.x = *reinterpret_cast<unsigned*>(&l01);
    lo.y = *reinterpret_cast<unsigned*>(&l23);
}

// ---------------------------------------------------------------------------
// K1: double LN on input (smem transpose tile). x is [c][voxel]; out [voxel][c]
// ---------------------------------------------------------------------------
__global__ void __launch_bounds__(128) ln_in_kernel(
        const float* __restrict__ x,
        const float* __restrict__ lw, const float* __restrict__ lb,
        const float* __restrict__ mw, const float* __restrict__ mb,
        float* __restrict__ out) {
    __shared__ float s[128 * 132];
    __shared__ float slw[128], slb[128], smw[128], smb[128];
    int tid = threadIdx.x;
    int vBase = blockIdx.x << 7;
    slw[tid] = lw[tid]; slb[tid] = lb[tid];
    smw[tid] = mw[tid]; smb[tid] = mb[tid];
    #pragma unroll 8
    for (int i = tid; i < 128 * 128; i += 128) {
        int c = i >> 7, v = i & 127;
        s[c * 132 + v] = x[c * LQ + vBase + v];
    }
    __syncthreads();
    int v = tid;
    float s1 = 0.f, s2 = 0.f;
    #pragma unroll 8
    for (int c = 0; c < 128; c++) { float t = s[c * 132 + v]; s1 += t; s2 += t * t; }
    float m = s1 * (1.f / 128.f);
    float var = s2 * (1.f / 128.f) - m * m;
    float rs = rsqrtf(var + 1e-6f);
    float t1 = 0.f, t2 = 0.f;
    #pragma unroll 8
    for (int c = 0; c < 128; c++) {
        float yy = (s[c * 132 + v] - m) * rs * slw[c] + slb[c];
        t1 += yy; t2 += yy * yy;
    }
    float m2 = t1 * (1.f / 128.f);
    float v2 = t2 * (1.f / 128.f) - m2 * m2;
    float rs2 = rsqrtf(v2 + 1e-5f);
    #pragma unroll 8
    for (int c = 0; c < 128; c++) {
        float yy = (s[c * 132 + v] - m) * rs * slw[c] + slb[c];
        s[c * 132 + v] = (yy - m2) * rs2 * smw[c] + smb[c];
    }
    __syncthreads();
    #pragma unroll 8
    for (int i = tid; i < 128 * 128; i += 128) {
        int vv = i >> 7, c = i & 127;
        out[(vBase + vv) * NC + c] = s[c * 132 + vv];
    }
}

// K11: LN over rows of g_res (row-major [voxel][c]), eps 1e-6
__global__ void ln_row_kernel(const float* __restrict__ in,
                              const float* __restrict__ lw, const float* __restrict__ lb,
                              float* __restrict__ out) {
    int v = (blockIdx.x * blockDim.x + threadIdx.x) >> 5;
    int lane = threadIdx.x & 31;
    float vals[4]; float s1 = 0.f, s2 = 0.f;
    #pragma unroll
    for (int i = 0; i < 4; i++) {
        int c = lane + (i << 5);
        float t = in[v * NC + c];
        vals[i] = t; s1 += t; s2 += t * t;
    }
    s1 = wsum(s1); s2 = wsum(s2);
    float m = s1 * (1.f / 128.f);
    float var = s2 * (1.f / 128.f) - m * m;
    float rs = rsqrtf(var + 1e-6f);
    #pragma unroll
    for (int i = 0; i < 4; i++) {
        int c = lane + (i << 5);
        out[v * NC + c] = (vals[i] - m) * rs * lw[c] + lb[c];
    }
}

// ---------------------------------------------------------------------------
// Tensor-core GEMM, bf16 3-term split with split-at-STS and double buffering.
// C[M,N] = A[M,K] * W[N,K]^T. BM=64, BN=64, BK=32, 128 threads (4 warps 2x2).
// smem holds bf16 hi/lo tiles (pad 40 -> conflict-free fragment LDS).
// ---------------------------------------------------------------------------
struct ALoadDirect {
    const float* A; int K4;
    __device__ __forceinline__ float4 load(int row, int k4) const {
        return reinterpret_cast<const float4*>(A)[row * K4 + k4];
    }
};
struct ALoadNormGather {
    const float* A;
    __device__ __forceinline__ float4 load(int row, int k4) const {
        int r = row >> 12, l = row & 4095, v;
        if (r == 0)      v = l;
        else if (r == 1) v = ((l & 15) << 8) | (((l >> 8) & 15) << 4) | ((l >> 4) & 15);
        else             v = (((l >> 4) & 15) << 8) | ((l & 15) << 4) | ((l >> 8) & 15);
        return reinterpret_cast<const float4*>(A + (v << 7))[k4];
    }
};
struct ALoadCat {
    const float* Y;
    __device__ __forceinline__ float4 load(int row, int k4) const {
        int r = k4 >> 5, c4 = k4 & 31;
        return reinterpret_cast<const float4*>(Y + ((r << 12) + row) * NC)[c4];
    }
};

struct EpiStore {
    float* C; int stride;
    __device__ __forceinline__ void run(int row, int col, float v) const {
        C[row * stride + col] = v;
    }
};
struct EpiProjRes {
    float* res; const float* bias; const float* x;
    __device__ __forceinline__ void run(int row, int col, float v) const {
        res[row * NC + col] = v + bias[col] + x[(col << 12) + row];
    }
};
struct EpiBiasGelu {
    float* C; const float* bias;
    __device__ __forceinline__ void run(int row, int col, float v) const {
        float g = v + bias[col];
        C[row * 512 + col] = 0.5f * g * (1.0f + erff(g * 0.70710678118654752f));
    }
};
struct EpiFc2 {
    float* out; const float* bias; const float* res;
    __device__ __forceinline__ void run(int row, int col, float v) const {
        out[(col << 12) + row] = v + bias[col] + res[row * NC + col];
    }
};

template <class AL, class EP>
__global__ void __launch_bounds__(128) gemm_mma(AL al, const float* __restrict__ W,
                                                int N, int K, EP ep) {
    // bf16 tiles, rows padded to 40 elements (80B) -> conflict-free LDS.32
    __shared__ __nv_bfloat16 Ah[2][64][40], Al[2][64][40];
    __shared__ __nv_bfloat16 Bh[2][64][40], Bl[2][64][40];

    const int tid = threadIdx.x, wid = tid >> 5, lane = tid & 31;
    const int g = lane >> 2, q = lane & 3;
    const int wm = wid & 1, wn = wid >> 1;
    const int rowBase = blockIdx.y << 6;
    const int colBase = blockIdx.x << 6;

    float4 pa[4], pb[4];
    float acc[2][4][4] = {};

    auto loadG = [&](int kt4) {
        #pragma unroll
        for (int i = 0; i < 4; i++) {
            int idx = tid + i * 128;          // 0..511
            int r = idx >> 3, c4 = idx & 7;
            pa[i] = al.load(rowBase + r, kt4 + c4);
        }
        #pragma unroll
        for (int i = 0; i < 4; i++) {
            int idx = tid + i * 128;
            int n = idx >> 3, c4 = idx & 7;
            int col = colBase + n;
            pb[i] = (col < N)
                ? *reinterpret_cast<const float4*>(W + (size_t)col * K + (kt4 + c4) * 4)
                : make_float4(0.f, 0.f, 0.f, 0.f);
        }
    };
    auto sts = [&](int buf) {
        #pragma unroll
        for (int i = 0; i < 4; i++) {
            int idx = tid + i * 128;
            int r = idx >> 3, c4 = idx & 7;
            uint2 hi, lo;
            split4(pa[i], hi, lo);
            *reinterpret_cast<uint2*>(&Ah[buf][r][c4 << 2]) = hi;
            *reinterpret_cast<uint2*>(&Al[buf][r][c4 << 2]) = lo;
        }
        #pragma unroll
        for (int i = 0; i < 4; i++) {
            int idx = tid + i * 128;
            int n = idx >> 3, c4 = idx & 7;
            uint2 hi, lo;
            split4(pb[i], hi, lo);
            *reinterpret_cast<uint2*>(&Bh[buf][n][c4 << 2]) = hi;
            *reinterpret_cast<uint2*>(&Bl[buf][n][c4 << 2]) = lo;
        }
    };

    loadG(0);
    sts(0);
    __syncthreads();

    const int T = K >> 5;
    for (int t = 0; t < T; t++) {
        if (t + 1 < T) loadG((t + 1) << 3);
        int cur = t & 1;
        #pragma unroll
        for (int ks = 0; ks < 32; ks += 16) {
            unsigned bhf[4][2], blf[4][2];
            #pragma unroll
            for (int nt = 0; nt < 4; nt++) {
                int col = wn * 32 + nt * 8 + g;
                bhf[nt][0] = *reinterpret_cast<const unsigned*>(&Bh[cur][col][ks + 2 * q]);
                bhf[nt][1] = *reinterpret_cast<const unsigned*>(&Bh[cur][col][ks + 2 * q + 8]);
                blf[nt][0] = *reinterpret_cast<const unsigned*>(&Bl[cur][col][ks + 2 * q]);
                blf[nt][1] = *reinterpret_cast<const unsigned*>(&Bl[cur][col][ks + 2 * q + 8]);
            }
            #pragma unroll
            for (int mt = 0; mt < 2; mt++) {
                int row = wm * 32 + mt * 16 + g;
                unsigned ah[4], alo[4];
                ah[0]  = *reinterpret_cast<const unsigned*>(&Ah[cur][row][ks + 2 * q]);
                ah[1]  = *reinterpret_cast<const unsigned*>(&Ah[cur][row + 8][ks + 2 * q]);
                ah[2]  = *reinterpret_cast<const unsigned*>(&Ah[cur][row][ks + 2 * q + 8]);
                ah[3]  = *reinterpret_cast<const unsigned*>(&Ah[cur][row + 8][ks + 2 * q + 8]);
                alo[0] = *reinterpret_cast<const unsigned*>(&Al[cur][row][ks + 2 * q]);
                alo[1] = *reinterpret_cast<const unsigned*>(&Al[cur][row + 8][ks + 2 * q]);
                alo[2] = *reinterpret_cast<const unsigned*>(&Al[cur][row][ks + 2 * q + 8]);
                alo[3] = *reinterpret_cast<const unsigned*>(&Al[cur][row + 8][ks + 2 * q + 8]);
                #pragma unroll
                for (int nt = 0; nt < 4; nt++) {
                    mma16816(acc[mt][nt], ah, bhf[nt]);
                    mma16816(acc[mt][nt], ah, blf[nt]);
                    mma16816(acc[mt][nt], alo, bhf[nt]);
                }
            }
        }
        if (t + 1 < T) {
            sts(1 - cur);
            __syncthreads();
        }
    }

    #pragma unroll
    for (int mt = 0; mt < 2; mt++) {
        int row = rowBase + wm * 32 + mt * 16 + g;
        #pragma unroll
        for (int nt = 0; nt < 4; nt++) {
            int col = colBase + wn * 32 + nt * 8 + 2 * q;
            if (col < N) {
                ep.run(row, col, acc[mt][nt][0]);
                ep.run(row + 8, col, acc[mt][nt][2]);
                if (col + 1 < N) {
                    ep.run(row, col + 1, acc[mt][nt][1]);
                    ep.run(row + 8, col + 1, acc[mt][nt][3]);
                }
            }
        }
    }
}

// ---------------------------------------------------------------------------
// K3: causal depthwise conv (D_CONV=4) + silu
// ---------------------------------------------------------------------------
__global__ void conv_kernel(const float* __restrict__ xz,
                            const float* __restrict__ cw, const float* __restrict__ cb,
                            float* __restrict__ xc) {
    int idx = blockIdx.x * 256 + threadIdx.x;
    int d = idx & 255;
    int rt = idx >> 8;
    int t = rt & 4095;
    float acc = cb[d];
    const float* base = xz + rt * 512 + d;
    #pragma unroll
    for (int k = 0; k < 4; k++) {
        int tt = t - 3 + k;
        if (tt >= 0) acc += cw[d * 4 + k] * base[(k - 3) * 512];
    }
    xc[idx] = acc / (1.0f + fast_exp(-acc));
}

// ---------------------------------------------------------------------------
// K5: dt_proj + softplus + precompute e1/du/silu(z)
// ---------------------------------------------------------------------------
__global__ void dt_kernel(const float* __restrict__ xdbl, const float* __restrict__ xc,
                          const float* __restrict__ xz,
                          const float* __restrict__ dtw, const float* __restrict__ dtb,
                          float* __restrict__ e1o, float* __restrict__ duo,
                          float* __restrict__ szo) {
    int row = blockIdx.x;
    int d = threadIdx.x;
    __shared__ float sdt[8];
    if (d < 8) sdt[d] = xdbl[row * 40 + d];
    __syncthreads();
    float acc = dtb[d];
    #pragma unroll
    for (int j = 0; j < 8; j++) acc += sdt[j] * dtw[d * 8 + j];
    float delta = softplusf_(acc);
    int o = row * DI + d;
    e1o[o] = fast_exp(-delta);
    duo[o] = delta * xc[o];
    float z = xz[row * 512 + 256 + d];
    szo[o] = z / (1.0f + fast_exp(-z));
}

// ---------------------------------------------------------------------------
// Chunked selective scan, 3 passes
// ---------------------------------------------------------------------------
__global__ void __launch_bounds__(256) scan1_kernel(const float* __restrict__ xdbl,
                                                    const float* __restrict__ e1g,
                                                    const float* __restrict__ dug,
                                                    const float* __restrict__ A_log,
                                                    float* __restrict__ Sg,
                                                    float* __restrict__ pg) {
    int bid = blockIdx.x;
    int r = bid / NCHUNK, chunk = bid % NCHUNK;
    int d = threadIdx.x;
    __shared__ float sB[CHUNK * DST];
    int rowBase = r * LQ + chunk * CHUNK;
    for (int i = d; i < CHUNK * DST; i += 256) {
        int st = i >> 4, n = i & 15;
        sB[i] = xdbl[(rowBase + st) * 40 + 8 + n];
    }
    bool fastok = true; float aRow[16];
    #pragma unroll
    for (int n = 0; n < 16; n++) {
        float a = fast_exp(A_log[d * 16 + n]);
        aRow[n] = -a;
        fastok = fastok && (fabsf(a - (float)(n + 1)) < 0.4f);
    }
    __syncthreads();
    float S[16];
    #pragma unroll
    for (int n = 0; n < 16; n++) S[n] = 0.f;
    float p = 1.f;
    const float* e1p = e1g + rowBase * DI + d;
    const float* dup = dug + rowBase * DI + d;
    if (fastok) {
        for (int st = 0; st < CHUNK; st++) {
            float e1 = e1p[st * DI], du = dup[st * DI];
            float e[17]; build_pows(e1, e);
            p *= e1;
            #pragma unroll
            for (int n = 0; n < 16; n++)
                S[n] = e[n + 1] * S[n] + du * sB[(st << 4) + n];
        }
    } else {
        for (int st = 0; st < CHUNK; st++) {
            float e1 = e1p[st * DI], du = dup[st * DI];
            float delta = -__logf(e1);
            p *= e1;
            #pragma unroll
            for (int n = 0; n < 16; n++)
                S[n] = fast_exp(aRow[n] * delta) * S[n] + du * sB[(st << 4) + n];
        }
    }
    int o = (bid * DI + d) * DST;
    #pragma unroll
    for (int n = 0; n < 16; n++) Sg[o + n] = S[n];
    pg[bid * DI + d] = p;
}

// scan2: carry scan, thread per (r, d, n). grid = NSEQ*16, 256 threads.
__global__ void __launch_bounds__(256) scan2_kernel(const float* __restrict__ Sg,
                                                    const float* __restrict__ pg,
                                                    const float* __restrict__ A_log,
                                                    float* __restrict__ h0g) {
    int b = blockIdx.x;            // r*16 + dblk
    int r = b >> 4, dblk = b & 15;
    int tid = threadIdx.x;
    int dg = tid >> 4, n = tid & 15;
    int d = dblk * 16 + dg;
    float a = fast_exp(A_log[d * 16 + n]);
    bool fast = fabsf(a - (float)(n + 1)) < 0.4f;
    float H = 0.f;
    for (int c = 0; c < NCHUNK; c++) {
        int bid = r * NCHUNK + c;
        int idx = (bid * DI + d) * DST + n;
        h0g[idx] = H;
        float S = Sg[idx];
        float p = pg[bid * DI + d];
        float pw;
        if (fast) {
            float p2 = p * p, p4 = p2 * p2, p8 = p4 * p4, p16 = p8 * p8;
            int e = n + 1;
            pw = 1.f;
            if (e & 1)  pw *= p;
            if (e & 2)  pw *= p2;
            if (e & 4)  pw *= p4;
            if (e & 8)  pw *= p8;
            if (e & 16) pw *= p16;
        } else {
            pw = fast_exp(a * __logf(fmaxf(p, 1e-38f)));
        }
        H = pw * H + S;
    }
}

__global__ void __launch_bounds__(256) scan3_kernel(const float* __restrict__ xdbl,
                                                    const float* __restrict__ e1g,
                                                    const float* __restrict__ dug,
                                                    const float* __restrict__ xcg,
                                                    const float* __restrict__ szg,
                                                    const float* __restrict__ A_log,
                                                    const float* __restrict__ Dp,
                                                    const float* __restrict__ h0g,
                                                    float* __restrict__ yg) {
    int bid = blockIdx.x;
    int r = bid / NCHUNK, chunk = bid % NCHUNK;
    int d = threadIdx.x;
    __shared__ float sB[CHUNK * DST];
    __shared__ float sC[CHUNK * DST];
    int rowBase = r * LQ + chunk * CHUNK;
    for (int i = d; i < CHUNK * DST; i += 256) {
        int st = i >> 4, n = i & 15;
        sB[i] = xdbl[(rowBase + st) * 40 + 8 + n];
        sC[i] = xdbl[(rowBase + st) * 40 + 24 + n];
    }
    bool fastok = true; float aRow[16];
    #pragma unroll
    for (int n = 0; n < 16; n++) {
        float a = fast_exp(A_log[d * 16 + n]);
        aRow[n] = -a;
        fastok = fastok && (fabsf(a - (float)(n + 1)) < 0.4f);
    }
    float h[16];
    {
        int o = (bid * DI + d) * DST;
        #pragma unroll
        for (int n = 0; n < 16; n++) h[n] = h0g[o + n];
    }
    float Dd = Dp[d];
    __syncthreads();
    const float* e1p = e1g + rowBase * DI + d;
    const float* dup = dug + rowBase * DI + d;
    const float* xcp = xcg + rowBase * DI + d;
    const float* szp = szg + rowBase * DI + d;
    float* yp = yg + rowBase * DI + d;
    if (fastok) {
        for (int st = 0; st < CHUNK; st++) {
            float e1 = e1p[st * DI], du = dup[st * DI];
            float u = xcp[st * DI], sz = szp[st * DI];
            float e[17]; build_pows(e1, e);
            float y0 = 0.f, y1 = 0.f, y2 = 0.f, y3 = 0.f;
            #pragma unroll
            for (int n = 0; n < 16; n++)
                h[n] = e[n + 1] * h[n] + du * sB[(st << 4) + n];
            #pragma unroll
            for (int n = 0; n < 16; n++) {
                float t = h[n] * sC[(st << 4) + n];
                if ((n & 3) == 0) y0 += t; else if ((n & 3) == 1) y1 += t;
                else if ((n & 3) == 2) y2 += t; else y3 += t;
            }
            float y = ((y0 + y1) + (y2 + y3)) + u * Dd;
            yp[st * DI] = y * sz;
        }
    } else {
        for (int st = 0; st < CHUNK; st++) {
            float e1 = e1p[st * DI], du = dup[st * DI];
            float u = xcp[st * DI], sz = szp[st * DI];
            float delta = -__logf(e1);
            float y = 0.f;
            #pragma unroll
            for (int n = 0; n < 16; n++) {
                h[n] = fast_exp(aRow[n] * delta) * h[n] + du * sB[(st << 4) + n];
                y += h[n] * sC[(st << 4) + n];
            }
            yp[st * DI] = (y + u * Dd) * sz;
        }
    }
}

// ---------------------------------------------------------------------------
// Host launch
// ---------------------------------------------------------------------------
extern "C" void kernel_launch(void* const* d_in, const int* in_sizes, int n_in,
                              void* d_out, int out_size) {
    const float* x        = (const float*)d_in[0];
    const float* ln_w     = (const float*)d_in[1];
    const float* ln_b     = (const float*)d_in[2];
    const float* mnorm_w  = (const float*)d_in[3];
    const float* mnorm_b  = (const float*)d_in[4];
    const float* in_proj_w= (const float*)d_in[5];
    const float* conv_w   = (const float*)d_in[6];
    const float* conv_b   = (const float*)d_in[7];
    const float* x_proj_w = (const float*)d_in[8];
    const float* dt_proj_w= (const float*)d_in[9];
    const float* dt_proj_b= (const float*)d_in[10];
    const float* A_log    = (const float*)d_in[11];
    const float* D_param  = (const float*)d_in[12];
    const float* out_proj_w=(const float*)d_in[13];
    const float* proj_w   = (const float*)d_in[14];
    const float* proj_b   = (const float*)d_in[15];
    const float* fc1_w    = (const float*)d_in[16];
    const float* fc1_b    = (const float*)d_in[17];
    const float* fc2_w    = (const float*)d_in[18];
    const float* fc2_b    = (const float*)d_in[19];

    float *norm, *xz, *xc, *xdbl, *e1, *du, *sz, *S, *p, *h0, *ygp, *y, *res, *hn, *fc1o;
    cudaGetSymbolAddress((void**)&norm, g_norm);
    cudaGetSymbolAddress((void**)&xz,   g_xz);
    cudaGetSymbolAddress((void**)&xc,   g_xc);
    cudaGetSymbolAddress((void**)&xdbl, g_xdbl);
    cudaGetSymbolAddress((void**)&e1,   g_e1);
    cudaGetSymbolAddress((void**)&du,   g_du);
    cudaGetSymbolAddress((void**)&sz,   g_sz);
    cudaGetSymbolAddress((void**)&S,    g_S);
    cudaGetSymbolAddress((void**)&p,    g_p);
    cudaGetSymbolAddress((void**)&h0,   g_h0);
    cudaGetSymbolAddress((void**)&ygp,  g_yg);
    cudaGetSymbolAddress((void**)&y,    g_y);
    cudaGetSymbolAddress((void**)&res,  g_res);
    cudaGetSymbolAddress((void**)&hn,   g_hn);
    cudaGetSymbolAddress((void**)&fc1o, g_fc1);

    // 1. double LN -> g_norm
    ln_in_kernel<<<32, 128>>>(x, ln_w, ln_b, mnorm_w, mnorm_b, norm);
    // 2. in_proj: 12288 x 512 (K=128)
    gemm_mma<<<dim3(8, 192), 128>>>(ALoadNormGather{norm}, in_proj_w, 512, 128,
                                    EpiStore{xz, 512});
    // 3. causal conv + silu -> g_xc
    conv_kernel<<<NROW * DI / 256, 256>>>(xz, conv_w, conv_b, xc);
    // 4. x_proj: 12288 x 40 (K=256)
    gemm_mma<<<dim3(1, 192), 128>>>(ALoadDirect{xc, 64}, x_proj_w, 40, 256,
                                    EpiStore{xdbl, 40});
    // 5. dt_proj + softplus + precompute e1/du/silu(z)
    dt_kernel<<<NROW, 256>>>(xdbl, xc, xz, dt_proj_w, dt_proj_b, e1, du, sz);
    // 6-8. chunked selective scan
    scan1_kernel<<<NSEQ * NCHUNK, 256>>>(xdbl, e1, du, A_log, S, p);
    scan2_kernel<<<NSEQ * 16, 256>>>(S, p, A_log, h0);
    scan3_kernel<<<NSEQ * NCHUNK, 256>>>(xdbl, e1, du, xc, sz, A_log, D_param, h0, ygp);
    // 9. out_proj: 12288 x 128 (K=256)
    gemm_mma<<<dim3(2, 192), 128>>>(ALoadDirect{ygp, 64}, out_proj_w, 128, 256,
                                    EpiStore{y, 128});
    // 10. proj + bias + x residual: 4096 x 128 (K=384)
    gemm_mma<<<dim3(2, 64), 128>>>(ALoadCat{y}, proj_w, 128, 384,
                                   EpiProjRes{res, proj_b, x});
    // 11. LN(res) -> g_hn
    ln_row_kernel<<<512, 256>>>(res, ln_w, ln_b, hn);
    // 12. fc1 + bias + gelu: 4096 x 512 (K=128)
    gemm_mma<<<dim3(8, 64), 128>>>(ALoadDirect{hn, 32}, fc1_w, 512, 128,
                                   EpiBiasGelu{fc1o, fc1_b});
    // 13. fc2 + bias + residual, channel-major output: 4096 x 128 (K=512)
    gemm_mma<<<dim3(2, 64), 128>>>(ALoadDirect{fc1o, 128}, fc2_w, 128, 512,
                                   EpiFc2{(float*)d_out, fc2_b, res});
    (void)in_sizes; (void)n_in; (void)out_size;
}